// round 12
// baseline (speedup 1.0000x reference)
#include <cuda_runtime.h>

#define N_NODES   50000
#define N_EDGES   600000
#define FEA       128
#define NLAYER    3
#define NG        256
#define HDIM      256
#define LDIM      2
#define TOT_ADJ   (N_EDGES + N_NODES)

// ---------------- scratch (device globals; no allocation allowed) -------------
__device__ __align__(16) float g_h[N_NODES * FEA];   // post-GEMM features
__device__ __align__(16) float g_x[N_NODES * FEA];   // post-aggregation features
__device__ float g_dinv[N_NODES];
__device__ int   g_deg[N_NODES];
__device__ int   g_rowptr[N_NODES + 1];
__device__ int   g_cursor[N_NODES];
__device__ int   g_col[TOT_ADJ];
__device__ float g_val[TOT_ADJ];
__device__ int   g_start[NG + 1];
__device__ __align__(16) float g_pooled[NG * FEA];
__device__ __align__(16) float g_hidden[NG * HDIM];
__device__ int   g_is64;

// index helper: element i of a buffer that is either int32 or int64(LE, small)
__device__ __forceinline__ int ld_idx(const int* p, int i, int is64) {
    return is64 ? p[2 * i] : p[i];       // low word (values < 2^31)
}

// ---------------- dtype detection ---------------------------------------------
__global__ void k_detect(const int* __restrict__ ei) {
    int acc = 0;
    #pragma unroll
    for (int i = 1; i < 256; i += 2) acc |= ei[i];
    g_is64 = (acc == 0) ? 1 : 0;
}

// ---------------- CSR build ---------------------------------------------------
__global__ void k_init() {
    int i = blockIdx.x * blockDim.x + threadIdx.x;
    if (i < N_NODES) { g_deg[i] = 1; g_cursor[i] = 0; }   // 1 = self loop
}

__global__ void k_count(const int* __restrict__ ei) {
    int e = blockIdx.x * blockDim.x + threadIdx.x;
    if (e < N_EDGES) atomicAdd(&g_deg[ld_idx(ei, N_EDGES + e, g_is64)], 1);
}

// single-block exclusive scan of g_deg -> g_rowptr; also computes g_dinv
__global__ void k_scan() {
    __shared__ int s[1024];
    const int t = threadIdx.x;
    const int CH = (N_NODES + 1023) / 1024;          // 49
    int b = t * CH;
    int e = min(b + CH, N_NODES);
    int sum = 0;
    for (int i = b; i < e; i++) {
        int d = g_deg[i];
        g_dinv[i] = rsqrtf((float)d);                // fused dinv
        sum += d;
    }
    s[t] = sum;
    __syncthreads();
    for (int off = 1; off < 1024; off <<= 1) {
        int v = (t >= off) ? s[t - off] : 0;
        __syncthreads();
        s[t] += v;
        __syncthreads();
    }
    int excl = s[t] - sum;
    for (int i = b; i < e; i++) { g_rowptr[i] = excl; excl += g_deg[i]; }
    if (t == 1023) g_rowptr[N_NODES] = s[1023];
}

__global__ void k_fill(const int* __restrict__ ei) {
    int t = blockIdx.x * blockDim.x + threadIdx.x;
    int s, d;
    if (t < N_EDGES) {
        int is64 = g_is64;
        s = ld_idx(ei, t, is64);
        d = ld_idx(ei, N_EDGES + t, is64);
    } else if (t < TOT_ADJ) {
        s = d = t - N_EDGES;                  // self loop
    } else return;
    int idx = g_rowptr[d] + atomicAdd(&g_cursor[d], 1);
    g_col[idx] = s;
    g_val[idx] = g_dinv[s] * g_dinv[d];
}

// ------------- 3xTF32 tensor-core GEMM: g_h = A[M,128] @ W[128,128] -----------
// v = hi + lo (hi = tf32(v), lo = tf32(v - hi)); acc += hi*hi + hi*lo + lo*hi.
// block: 256 threads (8 warps, 2x4 warp grid), A tile 64x128, W 128x128.
#define AS_STRIDE 132
#define WS_STRIDE 136
#define A_WORDS   (64  * AS_STRIDE)
#define W_WORDS   (128 * WS_STRIDE)
#define SMEM_TC   ((2 * A_WORDS + 2 * W_WORDS) * 4)   // ~202 KB

__device__ __forceinline__ unsigned f2tf(float f) {
    unsigned r;
    asm("cvt.rna.tf32.f32 %0, %1;" : "=r"(r) : "f"(f));
    return r;
}
__device__ __forceinline__ void split_tf(float f, unsigned& hi, unsigned& lo) {
    hi = f2tf(f);
    lo = f2tf(f - __uint_as_float(hi));
}

__global__ __launch_bounds__(256, 1)
void k_gemm_tc(const float* __restrict__ A, const float* __restrict__ W) {
    extern __shared__ unsigned sm[];
    unsigned* Ah = sm;                       // [64][AS_STRIDE]
    unsigned* Al = Ah + A_WORDS;
    unsigned* Wh = Al + A_WORDS;             // [128][WS_STRIDE]
    unsigned* Wl = Wh + W_WORDS;

    if (A == nullptr) A = g_x;               // layers 1,2 read g_x

    const int tid  = threadIdx.x;
    const int base = blockIdx.x * 64;

    // stage A tile (64x128): 2048 float4 -> 8 per thread
    {
        const float4* A4 = (const float4*)A;
        #pragma unroll
        for (int i = 0; i < 8; i++) {
            int idx  = tid + i * 256;
            int row  = idx >> 5;
            int col4 = idx & 31;
            int grow = min(base + row, N_NODES - 1);
            float4 v = A4[grow * 32 + col4];
            uint4 h, l;
            split_tf(v.x, h.x, l.x); split_tf(v.y, h.y, l.y);
            split_tf(v.z, h.z, l.z); split_tf(v.w, h.w, l.w);
            *(uint4*)&Ah[row * AS_STRIDE + col4 * 4] = h;
            *(uint4*)&Al[row * AS_STRIDE + col4 * 4] = l;
        }
        // stage W (128x128): 4096 float4 -> 16 per thread
        const float4* W4 = (const float4*)W;
        #pragma unroll
        for (int i = 0; i < 16; i++) {
            int idx  = tid + i * 256;
            int row  = idx >> 5;
            int col4 = idx & 31;
            float4 v = W4[idx];
            uint4 h, l;
            split_tf(v.x, h.x, l.x); split_tf(v.y, h.y, l.y);
            split_tf(v.z, h.z, l.z); split_tf(v.w, h.w, l.w);
            *(uint4*)&Wh[row * WS_STRIDE + col4 * 4] = h;
            *(uint4*)&Wl[row * WS_STRIDE + col4 * 4] = l;
        }
    }
    __syncthreads();

    const int lane = tid & 31;
    const int wid  = tid >> 5;
    const int mrow = (wid & 1) * 32;          // 2 warps along M (64 rows)
    const int ncol = (wid >> 1) * 32;         // 4 warps along N (128 cols)
    const int r    = lane >> 2;
    const int c    = lane & 3;

    float acc[2][4][4];
    #pragma unroll
    for (int m = 0; m < 2; m++)
        #pragma unroll
        for (int n = 0; n < 4; n++)
            #pragma unroll
            for (int q = 0; q < 4; q++) acc[m][n][q] = 0.f;

    #define MMA(d, av, bv)                                                    \
        asm volatile(                                                         \
            "mma.sync.aligned.m16n8k8.row.col.f32.tf32.tf32.f32 "             \
            "{%0,%1,%2,%3}, {%4,%5,%6,%7}, {%8,%9}, {%0,%1,%2,%3};"           \
            : "+f"(d[0]), "+f"(d[1]), "+f"(d[2]), "+f"(d[3])                  \
            : "r"(av[0]), "r"(av[1]), "r"(av[2]), "r"(av[3]),                 \
              "r"(bv[0]), "r"(bv[1]))

    for (int ks = 0; ks < 16; ks++) {
        const int k0 = ks * 8;
        unsigned ah[2][4], al[2][4];
        #pragma unroll
        for (int m = 0; m < 2; m++) {
            int rb = mrow + m * 16 + r;
            int o0 = rb * AS_STRIDE + k0 + c;
            int o1 = (rb + 8) * AS_STRIDE + k0 + c;
            ah[m][0] = Ah[o0];     ah[m][1] = Ah[o1];
            ah[m][2] = Ah[o0 + 4]; ah[m][3] = Ah[o1 + 4];
            al[m][0] = Al[o0];     al[m][1] = Al[o1];
            al[m][2] = Al[o0 + 4]; al[m][3] = Al[o1 + 4];
        }
        unsigned bh[4][2], bl[4][2];
        #pragma unroll
        for (int n = 0; n < 4; n++) {
            int nb = ncol + n * 8 + r;
            int o0 = (k0 + c) * WS_STRIDE + nb;
            int o1 = (k0 + 4 + c) * WS_STRIDE + nb;
            bh[n][0] = Wh[o0]; bh[n][1] = Wh[o1];
            bl[n][0] = Wl[o0]; bl[n][1] = Wl[o1];
        }
        #pragma unroll
        for (int m = 0; m < 2; m++)
            #pragma unroll
            for (int n = 0; n < 4; n++) {
                MMA(acc[m][n], al[m], bh[n]);   // lo*hi
                MMA(acc[m][n], ah[m], bl[n]);   // hi*lo
                MMA(acc[m][n], ah[m], bh[n]);   // hi*hi
            }
    }
    #undef MMA

    #pragma unroll
    for (int m = 0; m < 2; m++) {
        int row0 = base + mrow + m * 16 + r;
        #pragma unroll
        for (int n = 0; n < 4; n++) {
            int col = ncol + n * 8 + 2 * c;
            if (row0 < N_NODES)
                *(float2*)&g_h[row0 * 128 + col] =
                    make_float2(acc[m][n][0], acc[m][n][1]);
            if (row0 + 8 < N_NODES)
                *(float2*)&g_h[(row0 + 8) * 128 + col] =
                    make_float2(acc[m][n][2], acc[m][n][3]);
        }
    }
}

// ---------------- CSR aggregation: g_x[v] = relu(sum_j val*h[col] + bg) -------
__global__ void k_agg(const float* __restrict__ bgl) {
    int warp = (blockIdx.x * blockDim.x + threadIdx.x) >> 5;
    int lane = threadIdx.x & 31;
    if (warp >= N_NODES) return;
    int r0 = g_rowptr[warp], r1 = g_rowptr[warp + 1];
    float ax = 0.f, ay = 0.f, az = 0.f, aw = 0.f;
    for (int j = r0; j < r1; j++) {
        int   s = g_col[j];
        float w = g_val[j];
        float4 hv = *(const float4*)&g_h[s * 128 + lane * 4];
        ax = fmaf(w, hv.x, ax);
        ay = fmaf(w, hv.y, ay);
        az = fmaf(w, hv.z, az);
        aw = fmaf(w, hv.w, aw);
    }
    float4 b = *(const float4*)&bgl[lane * 4];
    float4 o;
    o.x = fmaxf(ax + b.x, 0.f);
    o.y = fmaxf(ay + b.y, 0.f);
    o.z = fmaxf(az + b.z, 0.f);
    o.w = fmaxf(aw + b.w, 0.f);
    *(float4*)&g_x[warp * 128 + lane * 4] = o;
}

// ---------------- pooling -----------------------------------------------------
__global__ void k_start(const int* __restrict__ batch) {
    int g = blockIdx.x * blockDim.x + threadIdx.x;
    if (g > NG) return;
    int is64 = g_is64;
    int lo = 0, hi = N_NODES;
    while (lo < hi) {
        int mid = (lo + hi) >> 1;
        if (ld_idx(batch, mid, is64) < g) lo = mid + 1; else hi = mid;
    }
    g_start[g] = lo;
}

__global__ void k_pool() {
    int g = blockIdx.x, f = threadIdx.x;   // 128 threads
    int s = g_start[g], e = g_start[g + 1];
    float sum = 0.f;
    for (int n = s; n < e; n++) sum += g_x[n * 128 + f];
    int c = e - s;
    g_pooled[g * 128 + f] = sum / (float)max(c, 1);
}

// ---------------- MLP head ----------------------------------------------------
__global__ void k_mlp1(const float* __restrict__ w1, const float* __restrict__ b1) {
    __shared__ float pr[128];
    int g = blockIdx.x, j = threadIdx.x;   // 256 threads
    if (j < 128) pr[j] = g_pooled[g * 128 + j];
    __syncthreads();
    float acc = b1[j];
    #pragma unroll 4
    for (int k = 0; k < 128; k++) acc = fmaf(pr[k], w1[k * 256 + j], acc);
    g_hidden[g * 256 + j] = fmaxf(acc, 0.f);
}

__global__ void k_mlp2(const float* __restrict__ w2, const float* __restrict__ b2,
                       float* __restrict__ out) {
    int g = blockIdx.x;
    int w = threadIdx.x >> 5;
    int lane = threadIdx.x & 31;
    float acc = 0.f;
    #pragma unroll
    for (int k = lane; k < 256; k += 32)
        acc = fmaf(g_hidden[g * 256 + k], w2[k * 2 + w], acc);
    #pragma unroll
    for (int off = 16; off; off >>= 1)
        acc += __shfl_down_sync(0xffffffffu, acc, off);
    if (lane == 0) out[g * 2 + w] = acc + b2[w];
}

// ---------------- launch ------------------------------------------------------
extern "C" void kernel_launch(void* const* d_in, const int* in_sizes, int n_in,
                              void* d_out, int out_size) {
    // Identify inputs by element count (all distinct) — robust to ordering.
    const float *x = 0, *Wg = 0, *bg = 0, *w1 = 0, *b1 = 0, *w2 = 0, *b2 = 0;
    const int *ei = 0, *batch = 0;
    for (int i = 0; i < n_in; i++) {
        switch (in_sizes[i]) {
            case N_NODES * FEA:        x     = (const float*)d_in[i]; break;
            case NLAYER * FEA * FEA:   Wg    = (const float*)d_in[i]; break;
            case NLAYER * FEA:         bg    = (const float*)d_in[i]; break;
            case FEA * HDIM:           w1    = (const float*)d_in[i]; break;
            case HDIM:                 b1    = (const float*)d_in[i]; break;
            case HDIM * LDIM:          w2    = (const float*)d_in[i]; break;
            case LDIM:                 b2    = (const float*)d_in[i]; break;
            case 2 * N_EDGES:          ei    = (const int*)d_in[i];   break;
            case N_NODES:              batch = (const int*)d_in[i];   break;
        }
    }
    float* out = (float*)d_out;

    cudaFuncSetAttribute(k_gemm_tc, cudaFuncAttributeMaxDynamicSharedMemorySize,
                         SMEM_TC);

    k_detect<<<1, 1>>>(ei);
    k_init <<<(N_NODES + 255) / 256, 256>>>();
    k_count<<<(N_EDGES + 255) / 256, 256>>>(ei);
    k_scan <<<1, 1024>>>();
    k_fill <<<(TOT_ADJ + 255) / 256, 256>>>(ei);

    const int gemm_blocks = (N_NODES + 63) / 64;     // 782
    for (int l = 0; l < NLAYER; l++) {
        const float* A = (l == 0) ? x : nullptr;     // nullptr -> g_x inside
        k_gemm_tc<<<gemm_blocks, 256, SMEM_TC>>>(A, Wg + l * FEA * FEA);
        k_agg <<<(N_NODES * 32 + 255) / 256, 256>>>(bg + l * FEA);
    }

    k_start<<<2, 256>>>(batch);
    k_pool <<<NG, 128>>>();
    k_mlp1 <<<NG, 256>>>(w1, b1);
    k_mlp2 <<<NG, 64>>>(w2, b2, out);
}

// round 13
// speedup vs baseline: 1.3699x; 1.3699x over previous
#include <cuda_runtime.h>

#define N_NODES   50000
#define N_EDGES   600000
#define FEA       128
#define NLAYER    3
#define NG        256
#define HDIM      256
#define LDIM      2
#define TOT_ADJ   (N_EDGES + N_NODES)

#define SCAN_BLK  512
#define SCAN_GRID ((N_NODES + SCAN_BLK - 1) / SCAN_BLK)   // 98

// ---------------- scratch (device globals; no allocation allowed) -------------
__device__ __align__(16) float g_h[N_NODES * FEA];   // post-GEMM features
__device__ __align__(16) float g_x[N_NODES * FEA];   // post-aggregation features
__device__ float g_dinv[N_NODES];
__device__ int   g_deg[N_NODES];
__device__ int   g_rowptr[N_NODES + 1];
__device__ int   g_cursor[N_NODES];
__device__ int   g_col[TOT_ADJ];
__device__ float g_val[TOT_ADJ];
__device__ int   g_bsum[SCAN_GRID];
__device__ int   g_boff[SCAN_GRID];
__device__ int   g_start[NG + 1];
__device__ __align__(16) float g_pooled[NG * FEA];
__device__ __align__(16) float g_hidden[NG * HDIM];
__device__ int   g_is64;

// index helper: element i of a buffer that is either int32 or int64(LE, small)
__device__ __forceinline__ int ld_idx(const int* p, int i, int is64) {
    return is64 ? p[2 * i] : p[i];       // low word (values < 2^31)
}

// ---------------- dtype detection ---------------------------------------------
__global__ void k_detect(const int* __restrict__ ei) {
    int acc = 0;
    #pragma unroll
    for (int i = 1; i < 256; i += 2) acc |= ei[i];
    g_is64 = (acc == 0) ? 1 : 0;
}

// ---------------- CSR build ---------------------------------------------------
__global__ void k_init() {
    int i = blockIdx.x * blockDim.x + threadIdx.x;
    if (i < N_NODES) { g_deg[i] = 1; g_cursor[i] = 0; }   // 1 = self loop
}

__global__ void k_count(const int* __restrict__ ei) {
    int e = blockIdx.x * blockDim.x + threadIdx.x;
    if (e < N_EDGES) atomicAdd(&g_deg[ld_idx(ei, N_EDGES + e, g_is64)], 1);
}

// ---- parallel scan, phase 1: per-block exclusive scan + block sum + dinv -----
__global__ void k_scan1() {
    __shared__ int s[SCAN_BLK];
    const int t = threadIdx.x;
    const int gidx = blockIdx.x * SCAN_BLK + t;
    int v = 0;
    if (gidx < N_NODES) {
        v = g_deg[gidx];
        g_dinv[gidx] = rsqrtf((float)v);
    }
    s[t] = v;
    __syncthreads();
    #pragma unroll
    for (int off = 1; off < SCAN_BLK; off <<= 1) {
        int u = (t >= off) ? s[t - off] : 0;
        __syncthreads();
        s[t] += u;
        __syncthreads();
    }
    if (gidx < N_NODES) g_rowptr[gidx] = s[t] - v;     // local exclusive
    if (t == SCAN_BLK - 1) g_bsum[blockIdx.x] = s[t];  // block total
}

// ---- phase 2: scan the 98 block sums (1 tiny block) --------------------------
__global__ void k_scan2() {
    if (threadIdx.x == 0) {
        int acc = 0;
        for (int b = 0; b < SCAN_GRID; b++) {
            g_boff[b] = acc;
            acc += g_bsum[b];
        }
        g_rowptr[N_NODES] = acc;    // == TOT_ADJ
    }
}

// ---- phase 3: add block offsets ----------------------------------------------
__global__ void k_scan3() {
    int gidx = blockIdx.x * SCAN_BLK + threadIdx.x;
    if (gidx < N_NODES) g_rowptr[gidx] += g_boff[blockIdx.x];
}

__global__ void k_fill(const int* __restrict__ ei) {
    int t = blockIdx.x * blockDim.x + threadIdx.x;
    int s, d;
    if (t < N_EDGES) {
        int is64 = g_is64;
        s = ld_idx(ei, t, is64);
        d = ld_idx(ei, N_EDGES + t, is64);
    } else if (t < TOT_ADJ) {
        s = d = t - N_EDGES;                  // self loop
    } else return;
    int idx = g_rowptr[d] + atomicAdd(&g_cursor[d], 1);
    g_col[idx] = s;
    g_val[idx] = g_dinv[s] * g_dinv[d];
}

// ---------------- GEMM: g_h[M,128] = A[M,128] @ W[128,128] (fp32 FFMA) --------
// block: 256 threads, tile 64 rows x 128 cols, W fully in smem.
#define GEMM_SMEM ((128 * 128 + 16 * 68) * 4)
__global__ void k_gemm(const float* __restrict__ A, const float* __restrict__ W) {
    extern __shared__ float smem[];
    float* Ws = smem;                 // [128][128]
    float* As = smem + 128 * 128;     // [16][68] padded

    if (A == nullptr) A = g_x;        // layers 1,2 read the device-global buffer

    const int tid = threadIdx.x;
    {
        const float4* W4 = (const float4*)W;
        float4* Ws4 = (float4*)Ws;
        #pragma unroll
        for (int i = 0; i < 16; i++) Ws4[tid + i * 256] = W4[tid + i * 256];
    }

    const int tx = tid & 15;          // col group (8 cols)
    const int ty = tid >> 4;          // row group (4 rows)
    const int base = blockIdx.x * 64;

    float acc[4][8];
    #pragma unroll
    for (int i = 0; i < 4; i++)
        #pragma unroll
        for (int j = 0; j < 8; j++) acc[i][j] = 0.f;

    const int lr = tid >> 2;          // 0..63 row within tile for loading
    const int lq = tid & 3;           // 0..3  k-quad for loading
    const int gr = min(base + lr, N_NODES - 1);

    for (int k0 = 0; k0 < 128; k0 += 16) {
        __syncthreads();
        float4 v = *(const float4*)&A[gr * 128 + k0 + lq * 4];
        As[(lq * 4 + 0) * 68 + lr] = v.x;
        As[(lq * 4 + 1) * 68 + lr] = v.y;
        As[(lq * 4 + 2) * 68 + lr] = v.z;
        As[(lq * 4 + 3) * 68 + lr] = v.w;
        __syncthreads();

        #pragma unroll
        for (int kk = 0; kk < 16; kk++) {
            float4 a4 = *(const float4*)&As[kk * 68 + ty * 4];
            float4 b0 = *(const float4*)&Ws[(k0 + kk) * 128 + tx * 8];
            float4 b1 = *(const float4*)&Ws[(k0 + kk) * 128 + tx * 8 + 4];
            float a[4] = {a4.x, a4.y, a4.z, a4.w};
            float bb[8] = {b0.x, b0.y, b0.z, b0.w, b1.x, b1.y, b1.z, b1.w};
            #pragma unroll
            for (int i = 0; i < 4; i++)
                #pragma unroll
                for (int j = 0; j < 8; j++)
                    acc[i][j] = fmaf(a[i], bb[j], acc[i][j]);
        }
    }

    #pragma unroll
    for (int i = 0; i < 4; i++) {
        int row = base + ty * 4 + i;
        if (row < N_NODES) {
            float4 o0 = make_float4(acc[i][0], acc[i][1], acc[i][2], acc[i][3]);
            float4 o1 = make_float4(acc[i][4], acc[i][5], acc[i][6], acc[i][7]);
            *(float4*)&g_h[row * 128 + tx * 8]     = o0;
            *(float4*)&g_h[row * 128 + tx * 8 + 4] = o1;
        }
    }
}

// ---------------- CSR aggregation: g_x[v] = relu(sum_j val*h[col] + bg) -------
__global__ void k_agg(const float* __restrict__ bgl) {
    int warp = (blockIdx.x * blockDim.x + threadIdx.x) >> 5;
    int lane = threadIdx.x & 31;
    if (warp >= N_NODES) return;
    int r0 = g_rowptr[warp], r1 = g_rowptr[warp + 1];
    float ax = 0.f, ay = 0.f, az = 0.f, aw = 0.f;
    for (int j = r0; j < r1; j++) {
        int   s = g_col[j];
        float w = g_val[j];
        float4 hv = *(const float4*)&g_h[s * 128 + lane * 4];
        ax = fmaf(w, hv.x, ax);
        ay = fmaf(w, hv.y, ay);
        az = fmaf(w, hv.z, az);
        aw = fmaf(w, hv.w, aw);
    }
    float4 b = *(const float4*)&bgl[lane * 4];
    float4 o;
    o.x = fmaxf(ax + b.x, 0.f);
    o.y = fmaxf(ay + b.y, 0.f);
    o.z = fmaxf(az + b.z, 0.f);
    o.w = fmaxf(aw + b.w, 0.f);
    *(float4*)&g_x[warp * 128 + lane * 4] = o;
}

// ---------------- pooling -----------------------------------------------------
__global__ void k_start(const int* __restrict__ batch) {
    int g = blockIdx.x * blockDim.x + threadIdx.x;
    if (g > NG) return;
    int is64 = g_is64;
    int lo = 0, hi = N_NODES;
    while (lo < hi) {
        int mid = (lo + hi) >> 1;
        if (ld_idx(batch, mid, is64) < g) lo = mid + 1; else hi = mid;
    }
    g_start[g] = lo;
}

__global__ void k_pool() {
    int g = blockIdx.x, f = threadIdx.x;   // 128 threads
    int s = g_start[g], e = g_start[g + 1];
    float sum = 0.f;
    for (int n = s; n < e; n++) sum += g_x[n * 128 + f];
    int c = e - s;
    g_pooled[g * 128 + f] = sum / (float)max(c, 1);
}

// ---------------- MLP head ----------------------------------------------------
__global__ void k_mlp1(const float* __restrict__ w1, const float* __restrict__ b1) {
    __shared__ float pr[128];
    int g = blockIdx.x, j = threadIdx.x;   // 256 threads
    if (j < 128) pr[j] = g_pooled[g * 128 + j];
    __syncthreads();
    float acc = b1[j];
    #pragma unroll 4
    for (int k = 0; k < 128; k++) acc = fmaf(pr[k], w1[k * 256 + j], acc);
    g_hidden[g * 256 + j] = fmaxf(acc, 0.f);
}

__global__ void k_mlp2(const float* __restrict__ w2, const float* __restrict__ b2,
                       float* __restrict__ out) {
    int g = blockIdx.x;
    int w = threadIdx.x >> 5;
    int lane = threadIdx.x & 31;
    float acc = 0.f;
    #pragma unroll
    for (int k = lane; k < 256; k += 32)
        acc = fmaf(g_hidden[g * 256 + k], w2[k * 2 + w], acc);
    #pragma unroll
    for (int off = 16; off; off >>= 1)
        acc += __shfl_down_sync(0xffffffffu, acc, off);
    if (lane == 0) out[g * 2 + w] = acc + b2[w];
}

// ---------------- launch ------------------------------------------------------
extern "C" void kernel_launch(void* const* d_in, const int* in_sizes, int n_in,
                              void* d_out, int out_size) {
    // Identify inputs by element count (all distinct) — robust to ordering.
    const float *x = 0, *Wg = 0, *bg = 0, *w1 = 0, *b1 = 0, *w2 = 0, *b2 = 0;
    const int *ei = 0, *batch = 0;
    for (int i = 0; i < n_in; i++) {
        switch (in_sizes[i]) {
            case N_NODES * FEA:        x     = (const float*)d_in[i]; break;
            case NLAYER * FEA * FEA:   Wg    = (const float*)d_in[i]; break;
            case NLAYER * FEA:         bg    = (const float*)d_in[i]; break;
            case FEA * HDIM:           w1    = (const float*)d_in[i]; break;
            case HDIM:                 b1    = (const float*)d_in[i]; break;
            case HDIM * LDIM:          w2    = (const float*)d_in[i]; break;
            case LDIM:                 b2    = (const float*)d_in[i]; break;
            case 2 * N_EDGES:          ei    = (const int*)d_in[i];   break;
            case N_NODES:              batch = (const int*)d_in[i];   break;
        }
    }
    float* out = (float*)d_out;

    cudaFuncSetAttribute(k_gemm, cudaFuncAttributeMaxDynamicSharedMemorySize,
                         GEMM_SMEM);

    k_detect<<<1, 1>>>(ei);
    k_init <<<(N_NODES + 255) / 256, 256>>>();
    k_count<<<(N_EDGES + 255) / 256, 256>>>(ei);
    k_scan1<<<SCAN_GRID, SCAN_BLK>>>();
    k_scan2<<<1, 32>>>();
    k_scan3<<<SCAN_GRID, SCAN_BLK>>>();
    k_fill <<<(TOT_ADJ + 255) / 256, 256>>>(ei);

    const int gemm_blocks = (N_NODES + 63) / 64;
    for (int l = 0; l < NLAYER; l++) {
        const float* A = (l == 0) ? x : nullptr;   // nullptr -> g_x inside
        k_gemm<<<gemm_blocks, 256, GEMM_SMEM>>>(A, Wg + l * FEA * FEA);
        k_agg <<<(N_NODES * 32 + 255) / 256, 256>>>(bg + l * FEA);
    }

    k_start<<<2, 256>>>(batch);
    k_pool <<<NG, 128>>>();
    k_mlp1 <<<NG, 256>>>(w1, b1);
    k_mlp2 <<<NG, 64>>>(w2, b2, out);
}

// round 15
// speedup vs baseline: 1.6407x; 1.1977x over previous
#include <cuda_runtime.h>

#define N_NODES   50000
#define N_EDGES   600000
#define FEA       128
#define NLAYER    3
#define NG        256
#define HDIM      256
#define LDIM      2
#define TOT_ADJ   (N_EDGES + N_NODES)

#define SCAN_BLK  512
#define SCAN_GRID ((N_NODES + SCAN_BLK - 1) / SCAN_BLK)   // 98

// ---------------- scratch (device globals; no allocation allowed) -------------
__device__ __align__(16) float g_h[N_NODES * FEA];   // post-GEMM features
__device__ __align__(16) float g_x[N_NODES * FEA];   // post-aggregation features
__device__ float g_dinv[N_NODES];
__device__ int   g_deg[N_NODES];
__device__ int   g_rowptr[N_NODES + 1];
__device__ int   g_cursor[N_NODES];
__device__ int   g_col[TOT_ADJ];
__device__ float g_val[TOT_ADJ];
__device__ int   g_bsum[SCAN_GRID];
__device__ int   g_boff[SCAN_GRID];
__device__ int   g_start[NG + 1];
__device__ __align__(16) float g_pooled[NG * FEA];
__device__ __align__(16) float g_hidden[NG * HDIM];
__device__ int   g_is64;

// index helper: element i of a buffer that is either int32 or int64(LE, small)
__device__ __forceinline__ int ld_idx(const int* p, int i, int is64) {
    return is64 ? p[2 * i] : p[i];       // low word (values < 2^31)
}

// ---------------- dtype detection ---------------------------------------------
__global__ void k_detect(const int* __restrict__ ei) {
    int acc = 0;
    #pragma unroll
    for (int i = 1; i < 256; i += 2) acc |= ei[i];
    g_is64 = (acc == 0) ? 1 : 0;
}

// ---------------- CSR build ---------------------------------------------------
__global__ void k_init() {
    int i = blockIdx.x * blockDim.x + threadIdx.x;
    if (i < N_NODES) { g_deg[i] = 1; g_cursor[i] = 0; }   // 1 = self loop
}

__global__ void k_count(const int* __restrict__ ei) {
    int e = blockIdx.x * blockDim.x + threadIdx.x;
    if (e < N_EDGES) atomicAdd(&g_deg[ld_idx(ei, N_EDGES + e, g_is64)], 1);
}

// ---- parallel scan, phase 1: per-block exclusive scan + block sum + dinv -----
__global__ void k_scan1() {
    __shared__ int s[SCAN_BLK];
    const int t = threadIdx.x;
    const int gidx = blockIdx.x * SCAN_BLK + t;
    int v = 0;
    if (gidx < N_NODES) {
        v = g_deg[gidx];
        g_dinv[gidx] = rsqrtf((float)v);
    }
    s[t] = v;
    __syncthreads();
    #pragma unroll
    for (int off = 1; off < SCAN_BLK; off <<= 1) {
        int u = (t >= off) ? s[t - off] : 0;
        __syncthreads();
        s[t] += u;
        __syncthreads();
    }
    if (gidx < N_NODES) g_rowptr[gidx] = s[t] - v;     // local exclusive
    if (t == SCAN_BLK - 1) g_bsum[blockIdx.x] = s[t];  // block total
}

// ---- phase 2: scan the 98 block sums (1 tiny block) --------------------------
__global__ void k_scan2() {
    if (threadIdx.x == 0) {
        int acc = 0;
        for (int b = 0; b < SCAN_GRID; b++) {
            g_boff[b] = acc;
            acc += g_bsum[b];
        }
        g_rowptr[N_NODES] = acc;    // == TOT_ADJ
    }
}

// ---- phase 3: add block offsets ----------------------------------------------
__global__ void k_scan3() {
    int gidx = blockIdx.x * SCAN_BLK + threadIdx.x;
    if (gidx < N_NODES) g_rowptr[gidx] += g_boff[blockIdx.x];
}

__global__ void k_fill(const int* __restrict__ ei) {
    int t = blockIdx.x * blockDim.x + threadIdx.x;
    int s, d;
    if (t < N_EDGES) {
        int is64 = g_is64;
        s = ld_idx(ei, t, is64);
        d = ld_idx(ei, N_EDGES + t, is64);
    } else if (t < TOT_ADJ) {
        s = d = t - N_EDGES;                  // self loop
    } else return;
    int idx = g_rowptr[d] + atomicAdd(&g_cursor[d], 1);
    g_col[idx] = s;
    g_val[idx] = g_dinv[s] * g_dinv[d];
}

// ---------------- GEMM: g_h[M,128] = A[M,128] @ W[128,128] (fp32 FFMA) --------
// 256 threads = 16x16 grid, 8x8 micro-tile -> 128x128 block tile.
// 16 smem words per 64 FMA = 0.25 w/FMA = crossbar break-even -> FMA-bound.
#define AST 132   // A panel stride in words; multiple of 4 for float4 alignment
#define GEMM_SMEM ((128 * 128 + 16 * AST) * 4)   // 65536 + 8448 B = ~74 KB
__global__ __launch_bounds__(256)
void k_gemm(const float* __restrict__ A, const float* __restrict__ W) {
    extern __shared__ float smem[];
    float* Ws = smem;                 // [128][128] row-major
    float* As = smem + 128 * 128;     // [16][AST]  k-major (transposed panel)

    if (A == nullptr) A = g_x;        // layers 1,2 read the device-global buffer

    const int tid = threadIdx.x;
    {   // load full W (64 KB), float4 x16 per thread
        const float4* W4 = (const float4*)W;
        float4* Ws4 = (float4*)Ws;
        #pragma unroll
        for (int i = 0; i < 16; i++) Ws4[tid + i * 256] = W4[tid + i * 256];
    }

    const int tx = tid & 15;          // col group (8 cols)
    const int ty = tid >> 4;          // row group (8 rows)
    const int base = blockIdx.x * 128;

    float acc[8][8];
    #pragma unroll
    for (int i = 0; i < 8; i++)
        #pragma unroll
        for (int j = 0; j < 8; j++) acc[i][j] = 0.f;

    for (int k0 = 0; k0 < 128; k0 += 16) {
        __syncthreads();
        // stage A panel [rows 0..127][k0..k0+15], transposed: As[k][m]
        #pragma unroll
        for (int i = 0; i < 2; i++) {
            int idx = tid + i * 256;              // 0..511 float4 slots
            int row = idx >> 2;                   // 0..127
            int q   = idx & 3;                    // k-quad
            int grow = min(base + row, N_NODES - 1);
            float4 v = *(const float4*)&A[grow * 128 + k0 + q * 4];
            As[(q * 4 + 0) * AST + row] = v.x;
            As[(q * 4 + 1) * AST + row] = v.y;
            As[(q * 4 + 2) * AST + row] = v.z;
            As[(q * 4 + 3) * AST + row] = v.w;
        }
        __syncthreads();

        #pragma unroll
        for (int kk = 0; kk < 16; kk++) {
            float4 a0 = *(const float4*)&As[kk * AST + ty * 8];
            float4 a1 = *(const float4*)&As[kk * AST + ty * 8 + 4];
            float4 b0 = *(const float4*)&Ws[(k0 + kk) * 128 + tx * 8];
            float4 b1 = *(const float4*)&Ws[(k0 + kk) * 128 + tx * 8 + 4];
            float a[8] = {a0.x, a0.y, a0.z, a0.w, a1.x, a1.y, a1.z, a1.w};
            float b[8] = {b0.x, b0.y, b0.z, b0.w, b1.x, b1.y, b1.z, b1.w};
            #pragma unroll
            for (int i = 0; i < 8; i++)
                #pragma unroll
                for (int j = 0; j < 8; j++)
                    acc[i][j] = fmaf(a[i], b[j], acc[i][j]);
        }
    }

    #pragma unroll
    for (int i = 0; i < 8; i++) {
        int row = base + ty * 8 + i;
        if (row < N_NODES) {
            *(float4*)&g_h[row * 128 + tx * 8] =
                make_float4(acc[i][0], acc[i][1], acc[i][2], acc[i][3]);
            *(float4*)&g_h[row * 128 + tx * 8 + 4] =
                make_float4(acc[i][4], acc[i][5], acc[i][6], acc[i][7]);
        }
    }
}

// ---------------- CSR aggregation: g_x[v] = relu(sum_j val*h[col] + bg) -------
// one warp per dst node; edge loop unrolled x2 for memory-level parallelism
__global__ void k_agg(const float* __restrict__ bgl) {
    int warp = (blockIdx.x * blockDim.x + threadIdx.x) >> 5;
    int lane = threadIdx.x & 31;
    if (warp >= N_NODES) return;
    int r0 = g_rowptr[warp], r1 = g_rowptr[warp + 1];
    float ax = 0.f, ay = 0.f, az = 0.f, aw = 0.f;
    int j = r0;
    for (; j + 1 < r1; j += 2) {
        int   s0 = g_col[j],     s1 = g_col[j + 1];
        float w0 = g_val[j];
        float w1 = g_val[j + 1];
        float4 h0 = *(const float4*)&g_h[s0 * 128 + lane * 4];
        float4 h1 = *(const float4*)&g_h[s1 * 128 + lane * 4];
        ax = fmaf(w0, h0.x, ax); ay = fmaf(w0, h0.y, ay);
        az = fmaf(w0, h0.z, az); aw = fmaf(w0, h0.w, aw);
        ax = fmaf(w1, h1.x, ax); ay = fmaf(w1, h1.y, ay);
        az = fmaf(w1, h1.z, az); aw = fmaf(w1, h1.w, aw);
    }
    if (j < r1) {
        int   s = g_col[j];
        float w = g_val[j];
        float4 hv = *(const float4*)&g_h[s * 128 + lane * 4];
        ax = fmaf(w, hv.x, ax); ay = fmaf(w, hv.y, ay);
        az = fmaf(w, hv.z, az); aw = fmaf(w, hv.w, aw);
    }
    float4 b = *(const float4*)&bgl[lane * 4];
    float4 o;
    o.x = fmaxf(ax + b.x, 0.f);
    o.y = fmaxf(ay + b.y, 0.f);
    o.z = fmaxf(az + b.z, 0.f);
    o.w = fmaxf(aw + b.w, 0.f);
    *(float4*)&g_x[warp * 128 + lane * 4] = o;
}

// ---------------- pooling -----------------------------------------------------
__global__ void k_start(const int* __restrict__ batch) {
    int g = blockIdx.x * blockDim.x + threadIdx.x;
    if (g > NG) return;
    int is64 = g_is64;
    int lo = 0, hi = N_NODES;
    while (lo < hi) {
        int mid = (lo + hi) >> 1;
        if (ld_idx(batch, mid, is64) < g) lo = mid + 1; else hi = mid;
    }
    g_start[g] = lo;
}

__global__ void k_pool() {
    int g = blockIdx.x, f = threadIdx.x;   // 128 threads
    int s = g_start[g], e = g_start[g + 1];
    float sum = 0.f;
    for (int n = s; n < e; n++) sum += g_x[n * 128 + f];
    int c = e - s;
    g_pooled[g * 128 + f] = sum / (float)max(c, 1);
}

// ---------------- MLP head ----------------------------------------------------
__global__ void k_mlp1(const float* __restrict__ w1, const float* __restrict__ b1) {
    __shared__ float pr[128];
    int g = blockIdx.x, j = threadIdx.x;   // 256 threads
    if (j < 128) pr[j] = g_pooled[g * 128 + j];
    __syncthreads();
    float acc = b1[j];
    #pragma unroll 4
    for (int k = 0; k < 128; k++) acc = fmaf(pr[k], w1[k * 256 + j], acc);
    g_hidden[g * 256 + j] = fmaxf(acc, 0.f);
}

__global__ void k_mlp2(const float* __restrict__ w2, const float* __restrict__ b2,
                       float* __restrict__ out) {
    int g = blockIdx.x;
    int w = threadIdx.x >> 5;
    int lane = threadIdx.x & 31;
    float acc = 0.f;
    #pragma unroll
    for (int k = lane; k < 256; k += 32)
        acc = fmaf(g_hidden[g * 256 + k], w2[k * 2 + w], acc);
    #pragma unroll
    for (int off = 16; off; off >>= 1)
        acc += __shfl_down_sync(0xffffffffu, acc, off);
    if (lane == 0) out[g * 2 + w] = acc + b2[w];
}

// ---------------- launch ------------------------------------------------------
extern "C" void kernel_launch(void* const* d_in, const int* in_sizes, int n_in,
                              void* d_out, int out_size) {
    // Identify inputs by element count (all distinct) — robust to ordering.
    const float *x = 0, *Wg = 0, *bg = 0, *w1 = 0, *b1 = 0, *w2 = 0, *b2 = 0;
    const int *ei = 0, *batch = 0;
    for (int i = 0; i < n_in; i++) {
        switch (in_sizes[i]) {
            case N_NODES * FEA:        x     = (const float*)d_in[i]; break;
            case NLAYER * FEA * FEA:   Wg    = (const float*)d_in[i]; break;
            case NLAYER * FEA:         bg    = (const float*)d_in[i]; break;
            case FEA * HDIM:           w1    = (const float*)d_in[i]; break;
            case HDIM:                 b1    = (const float*)d_in[i]; break;
            case HDIM * LDIM:          w2    = (const float*)d_in[i]; break;
            case LDIM:                 b2    = (const float*)d_in[i]; break;
            case 2 * N_EDGES:          ei    = (const int*)d_in[i];   break;
            case N_NODES:              batch = (const int*)d_in[i];   break;
        }
    }
    float* out = (float*)d_out;

    cudaFuncSetAttribute(k_gemm, cudaFuncAttributeMaxDynamicSharedMemorySize,
                         GEMM_SMEM);

    k_detect<<<1, 1>>>(ei);
    k_init <<<(N_NODES + 255) / 256, 256>>>();
    k_count<<<(N_EDGES + 255) / 256, 256>>>(ei);
    k_scan1<<<SCAN_GRID, SCAN_BLK>>>();
    k_scan2<<<1, 32>>>();
    k_scan3<<<SCAN_GRID, SCAN_BLK>>>();
    k_fill <<<(TOT_ADJ + 255) / 256, 256>>>(ei);

    const int gemm_blocks = (N_NODES + 127) / 128;   // 391
    for (int l = 0; l < NLAYER; l++) {
        const float* A = (l == 0) ? x : nullptr;     // nullptr -> g_x inside
        k_gemm<<<gemm_blocks, 256, GEMM_SMEM>>>(A, Wg + l * FEA * FEA);
        k_agg <<<(N_NODES * 32 + 255) / 256, 256>>>(bg + l * FEA);
    }

    k_start<<<2, 256>>>(batch);
    k_pool <<<NG, 128>>>();
    k_mlp1 <<<NG, 256>>>(w1, b1);
    k_mlp2 <<<NG, 64>>>(w2, b2, out);
}

// round 16
// speedup vs baseline: 1.7152x; 1.0454x over previous
#include <cuda_runtime.h>

#define N_NODES   50000
#define N_EDGES   600000
#define FEA       128
#define NLAYER    3
#define NG        256
#define HDIM      256
#define LDIM      2
#define TOT_ADJ   (N_EDGES + N_NODES)

#define SCAN_BLK  512
#define SCAN_GRID ((N_NODES + SCAN_BLK - 1) / SCAN_BLK)   // 98

// ---------------- scratch (device globals; no allocation allowed) -------------
__device__ __align__(16) float g_h[N_NODES * FEA];   // post-GEMM features
__device__ __align__(16) float g_x[N_NODES * FEA];   // post-aggregation features
__device__ float g_dinv[N_NODES];
__device__ int   g_deg[N_NODES];
__device__ int   g_rowptr[N_NODES + 1];
__device__ int   g_cursor[N_NODES];
__device__ int   g_col[TOT_ADJ];
__device__ float g_val[TOT_ADJ];
__device__ int   g_bsum[SCAN_GRID];
__device__ int   g_boff[SCAN_GRID];
__device__ int   g_start[NG + 1];
__device__ __align__(16) float g_pooled[NG * FEA];
__device__ __align__(16) float g_hidden[NG * HDIM];
__device__ int   g_is64;

// index helper: element i of a buffer that is either int32 or int64(LE, small)
__device__ __forceinline__ int ld_idx(const int* p, int i, int is64) {
    return is64 ? p[2 * i] : p[i];       // low word (values < 2^31)
}

// ---------------- dtype detection ---------------------------------------------
__global__ void k_detect(const int* __restrict__ ei) {
    int acc = 0;
    #pragma unroll
    for (int i = 1; i < 256; i += 2) acc |= ei[i];
    g_is64 = (acc == 0) ? 1 : 0;
}

// ---------------- CSR build ---------------------------------------------------
__global__ void k_init() {
    int i = blockIdx.x * blockDim.x + threadIdx.x;
    if (i < N_NODES) { g_deg[i] = 1; g_cursor[i] = 0; }   // 1 = self loop
}

__global__ void k_count(const int* __restrict__ ei) {
    int e = blockIdx.x * blockDim.x + threadIdx.x;
    if (e < N_EDGES) atomicAdd(&g_deg[ld_idx(ei, N_EDGES + e, g_is64)], 1);
}

// ---- parallel scan, phase 1: per-block exclusive scan + block sum + dinv -----
__global__ void k_scan1() {
    __shared__ int s[SCAN_BLK];
    const int t = threadIdx.x;
    const int gidx = blockIdx.x * SCAN_BLK + t;
    int v = 0;
    if (gidx < N_NODES) {
        v = g_deg[gidx];
        g_dinv[gidx] = rsqrtf((float)v);
    }
    s[t] = v;
    __syncthreads();
    #pragma unroll
    for (int off = 1; off < SCAN_BLK; off <<= 1) {
        int u = (t >= off) ? s[t - off] : 0;
        __syncthreads();
        s[t] += u;
        __syncthreads();
    }
    if (gidx < N_NODES) g_rowptr[gidx] = s[t] - v;     // local exclusive
    if (t == SCAN_BLK - 1) g_bsum[blockIdx.x] = s[t];  // block total
}

// ---- phase 2: scan the 98 block sums (1 tiny block) --------------------------
__global__ void k_scan2() {
    if (threadIdx.x == 0) {
        int acc = 0;
        for (int b = 0; b < SCAN_GRID; b++) {
            g_boff[b] = acc;
            acc += g_bsum[b];
        }
        g_rowptr[N_NODES] = acc;    // == TOT_ADJ
    }
}

// ---- phase 3: add block offsets ----------------------------------------------
__global__ void k_scan3() {
    int gidx = blockIdx.x * SCAN_BLK + threadIdx.x;
    if (gidx < N_NODES) g_rowptr[gidx] += g_boff[blockIdx.x];
}

__global__ void k_fill(const int* __restrict__ ei) {
    int t = blockIdx.x * blockDim.x + threadIdx.x;
    int s, d;
    if (t < N_EDGES) {
        int is64 = g_is64;
        s = ld_idx(ei, t, is64);
        d = ld_idx(ei, N_EDGES + t, is64);
    } else if (t < TOT_ADJ) {
        s = d = t - N_EDGES;                  // self loop
    } else return;
    int idx = g_rowptr[d] + atomicAdd(&g_cursor[d], 1);
    g_col[idx] = s;
    g_val[idx] = g_dinv[s] * g_dinv[d];
}

// ---------------- GEMM: g_h[M,128] = A[M,128] @ W[128,128] (fp32 FFMA) --------
// 256 threads = 16x16 grid, 8x8 micro-tile -> 128x128 block tile.
// A-panel global loads prefetched into registers one panel ahead, so LDG
// latency overlaps the previous panel's FMA block.
#define AST 132   // A panel stride in words; multiple of 4 for float4 alignment
#define GEMM_SMEM ((128 * 128 + 16 * AST) * 4)   // ~74 KB -> 3 blocks/SM
__global__ __launch_bounds__(256)
void k_gemm(const float* __restrict__ A, const float* __restrict__ W) {
    extern __shared__ float smem[];
    float* Ws = smem;                 // [128][128] row-major
    float* As = smem + 128 * 128;     // [16][AST]  k-major (transposed panel)

    if (A == nullptr) A = g_x;        // layers 1,2 read the device-global buffer

    const int tid = threadIdx.x;
    {   // load full W (64 KB), float4 x16 per thread
        const float4* W4 = (const float4*)W;
        float4* Ws4 = (float4*)Ws;
        #pragma unroll
        for (int i = 0; i < 16; i++) Ws4[tid + i * 256] = W4[tid + i * 256];
    }

    const int tx = tid & 15;          // col group (8 cols)
    const int ty = tid >> 4;          // row group (8 rows)
    const int base = blockIdx.x * 128;

    // loader coordinates: 512 float4 slots, 2 per thread
    const int lrow0 = (tid + 0)   >> 2;   // 0..63
    const int lq0   = (tid + 0)   & 3;
    const int lrow1 = (tid + 256) >> 2;   // 64..127
    const int lq1   = (tid + 256) & 3;
    const int grow0 = min(base + lrow0, N_NODES - 1);
    const int grow1 = min(base + lrow1, N_NODES - 1);

    float acc[8][8];
    #pragma unroll
    for (int i = 0; i < 8; i++)
        #pragma unroll
        for (int j = 0; j < 8; j++) acc[i][j] = 0.f;

    // prefetch panel 0
    float4 p0 = *(const float4*)&A[grow0 * 128 + 0 + lq0 * 4];
    float4 p1 = *(const float4*)&A[grow1 * 128 + 0 + lq1 * 4];

    for (int ks = 0; ks < 8; ks++) {
        const int k0 = ks * 16;
        __syncthreads();               // previous panel's compute done
        As[(lq0 * 4 + 0) * AST + lrow0] = p0.x;
        As[(lq0 * 4 + 1) * AST + lrow0] = p0.y;
        As[(lq0 * 4 + 2) * AST + lrow0] = p0.z;
        As[(lq0 * 4 + 3) * AST + lrow0] = p0.w;
        As[(lq1 * 4 + 0) * AST + lrow1] = p1.x;
        As[(lq1 * 4 + 1) * AST + lrow1] = p1.y;
        As[(lq1 * 4 + 2) * AST + lrow1] = p1.z;
        As[(lq1 * 4 + 3) * AST + lrow1] = p1.w;
        __syncthreads();
        if (ks < 7) {                  // prefetch next panel (LDG overlaps FMAs)
            p0 = *(const float4*)&A[grow0 * 128 + (k0 + 16) + lq0 * 4];
            p1 = *(const float4*)&A[grow1 * 128 + (k0 + 16) + lq1 * 4];
        }

        #pragma unroll
        for (int kk = 0; kk < 16; kk++) {
            float4 a0 = *(const float4*)&As[kk * AST + ty * 8];
            float4 a1 = *(const float4*)&As[kk * AST + ty * 8 + 4];
            float4 b0 = *(const float4*)&Ws[(k0 + kk) * 128 + tx * 8];
            float4 b1 = *(const float4*)&Ws[(k0 + kk) * 128 + tx * 8 + 4];
            float a[8] = {a0.x, a0.y, a0.z, a0.w, a1.x, a1.y, a1.z, a1.w};
            float b[8] = {b0.x, b0.y, b0.z, b0.w, b1.x, b1.y, b1.z, b1.w};
            #pragma unroll
            for (int i = 0; i < 8; i++)
                #pragma unroll
                for (int j = 0; j < 8; j++)
                    acc[i][j] = fmaf(a[i], b[j], acc[i][j]);
        }
    }

    #pragma unroll
    for (int i = 0; i < 8; i++) {
        int row = base + ty * 8 + i;
        if (row < N_NODES) {
            *(float4*)&g_h[row * 128 + tx * 8] =
                make_float4(acc[i][0], acc[i][1], acc[i][2], acc[i][3]);
            *(float4*)&g_h[row * 128 + tx * 8 + 4] =
                make_float4(acc[i][4], acc[i][5], acc[i][6], acc[i][7]);
        }
    }
}

// ---------------- CSR aggregation: g_x[v] = relu(sum_j val*h[col] + bg) -------
// one warp per dst node; edge loop unrolled x4 for memory-level parallelism
__global__ void k_agg(const float* __restrict__ bgl) {
    int warp = (blockIdx.x * blockDim.x + threadIdx.x) >> 5;
    int lane = threadIdx.x & 31;
    if (warp >= N_NODES) return;
    int r0 = g_rowptr[warp], r1 = g_rowptr[warp + 1];
    float ax = 0.f, ay = 0.f, az = 0.f, aw = 0.f;
    int j = r0;
    for (; j + 3 < r1; j += 4) {
        int s0 = g_col[j],     s1 = g_col[j + 1];
        int s2 = g_col[j + 2], s3 = g_col[j + 3];
        float w0 = g_val[j],     w1 = g_val[j + 1];
        float w2 = g_val[j + 2], w3 = g_val[j + 3];
        float4 h0 = *(const float4*)&g_h[s0 * 128 + lane * 4];
        float4 h1 = *(const float4*)&g_h[s1 * 128 + lane * 4];
        float4 h2 = *(const float4*)&g_h[s2 * 128 + lane * 4];
        float4 h3 = *(const float4*)&g_h[s3 * 128 + lane * 4];
        ax = fmaf(w0, h0.x, ax); ay = fmaf(w0, h0.y, ay);
        az = fmaf(w0, h0.z, az); aw = fmaf(w0, h0.w, aw);
        ax = fmaf(w1, h1.x, ax); ay = fmaf(w1, h1.y, ay);
        az = fmaf(w1, h1.z, az); aw = fmaf(w1, h1.w, aw);
        ax = fmaf(w2, h2.x, ax); ay = fmaf(w2, h2.y, ay);
        az = fmaf(w2, h2.z, az); aw = fmaf(w2, h2.w, aw);
        ax = fmaf(w3, h3.x, ax); ay = fmaf(w3, h3.y, ay);
        az = fmaf(w3, h3.z, az); aw = fmaf(w3, h3.w, aw);
    }
    for (; j < r1; j++) {
        int   s = g_col[j];
        float w = g_val[j];
        float4 hv = *(const float4*)&g_h[s * 128 + lane * 4];
        ax = fmaf(w, hv.x, ax); ay = fmaf(w, hv.y, ay);
        az = fmaf(w, hv.z, az); aw = fmaf(w, hv.w, aw);
    }
    float4 b = *(const float4*)&bgl[lane * 4];
    float4 o;
    o.x = fmaxf(ax + b.x, 0.f);
    o.y = fmaxf(ay + b.y, 0.f);
    o.z = fmaxf(az + b.z, 0.f);
    o.w = fmaxf(aw + b.w, 0.f);
    *(float4*)&g_x[warp * 128 + lane * 4] = o;
}

// ---------------- pooling -----------------------------------------------------
__global__ void k_start(const int* __restrict__ batch) {
    int g = blockIdx.x * blockDim.x + threadIdx.x;
    if (g > NG) return;
    int is64 = g_is64;
    int lo = 0, hi = N_NODES;
    while (lo < hi) {
        int mid = (lo + hi) >> 1;
        if (ld_idx(batch, mid, is64) < g) lo = mid + 1; else hi = mid;
    }
    g_start[g] = lo;
}

__global__ void k_pool() {
    int g = blockIdx.x, f = threadIdx.x;   // 128 threads
    int s = g_start[g], e = g_start[g + 1];
    float sum = 0.f;
    for (int n = s; n < e; n++) sum += g_x[n * 128 + f];
    int c = e - s;
    g_pooled[g * 128 + f] = sum / (float)max(c, 1);
}

// ---------------- MLP head ----------------------------------------------------
__global__ void k_mlp1(const float* __restrict__ w1, const float* __restrict__ b1) {
    __shared__ float pr[128];
    int g = blockIdx.x, j = threadIdx.x;   // 256 threads
    if (j < 128) pr[j] = g_pooled[g * 128 + j];
    __syncthreads();
    float acc = b1[j];
    #pragma unroll 4
    for (int k = 0; k < 128; k++) acc = fmaf(pr[k], w1[k * 256 + j], acc);
    g_hidden[g * 256 + j] = fmaxf(acc, 0.f);
}

__global__ void k_mlp2(const float* __restrict__ w2, const float* __restrict__ b2,
                       float* __restrict__ out) {
    int g = blockIdx.x;
    int w = threadIdx.x >> 5;
    int lane = threadIdx.x & 31;
    float acc = 0.f;
    #pragma unroll
    for (int k = lane; k < 256; k += 32)
        acc = fmaf(g_hidden[g * 256 + k], w2[k * 2 + w], acc);
    #pragma unroll
    for (int off = 16; off; off >>= 1)
        acc += __shfl_down_sync(0xffffffffu, acc, off);
    if (lane == 0) out[g * 2 + w] = acc + b2[w];
}

// ---------------- launch ------------------------------------------------------
extern "C" void kernel_launch(void* const* d_in, const int* in_sizes, int n_in,
                              void* d_out, int out_size) {
    // Identify inputs by element count (all distinct) — robust to ordering.
    const float *x = 0, *Wg = 0, *bg = 0, *w1 = 0, *b1 = 0, *w2 = 0, *b2 = 0;
    const int *ei = 0, *batch = 0;
    for (int i = 0; i < n_in; i++) {
        switch (in_sizes[i]) {
            case N_NODES * FEA:        x     = (const float*)d_in[i]; break;
            case NLAYER * FEA * FEA:   Wg    = (const float*)d_in[i]; break;
            case NLAYER * FEA:         bg    = (const float*)d_in[i]; break;
            case FEA * HDIM:           w1    = (const float*)d_in[i]; break;
            case HDIM:                 b1    = (const float*)d_in[i]; break;
            case HDIM * LDIM:          w2    = (const float*)d_in[i]; break;
            case LDIM:                 b2    = (const float*)d_in[i]; break;
            case 2 * N_EDGES:          ei    = (const int*)d_in[i];   break;
            case N_NODES:              batch = (const int*)d_in[i];   break;
        }
    }
    float* out = (float*)d_out;

    cudaFuncSetAttribute(k_gemm, cudaFuncAttributeMaxDynamicSharedMemorySize,
                         GEMM_SMEM);

    k_detect<<<1, 1>>>(ei);
    k_init <<<(N_NODES + 255) / 256, 256>>>();
    k_count<<<(N_EDGES + 255) / 256, 256>>>(ei);
    k_scan1<<<SCAN_GRID, SCAN_BLK>>>();
    k_scan2<<<1, 32>>>();
    k_scan3<<<SCAN_GRID, SCAN_BLK>>>();
    k_fill <<<(TOT_ADJ + 255) / 256, 256>>>(ei);

    const int gemm_blocks = (N_NODES + 127) / 128;   // 391
    for (int l = 0; l < NLAYER; l++) {
        const float* A = (l == 0) ? x : nullptr;     // nullptr -> g_x inside
        k_gemm<<<gemm_blocks, 256, GEMM_SMEM>>>(A, Wg + l * FEA * FEA);
        k_agg <<<(N_NODES * 32 + 255) / 256, 256>>>(bg + l * FEA);
    }

    k_start<<<2, 256>>>(batch);
    k_pool <<<NG, 128>>>();
    k_mlp1 <<<NG, 256>>>(w1, b1);
    k_mlp2 <<<NG, 64>>>(w2, b2, out);
}